// round 15
// baseline (speedup 1.0000x reference)
#include <cuda_runtime.h>
#include <math_constants.h>

// Problem constants
#define NUM_VARS 64
#define KK       32
#define NUM_CATS 256
#define NUM_INPUT (NUM_VARS * KK)   // 2048
#define LL       4
#define EE       16384
#define NN       8192
#define CC       4
#define BB       1024
#define Q16      128                // uint4-groups per row (1024 u16 = 128 x 16B)
#define TOTAL_NODES (NUM_INPUT + LL * NN)  // 34816
#define NCHUNK   64
#define MAX_NPB  14                 // max nodes per block per layer

#define GRID_BLOCKS 592             // 4 blocks/SM on 148 SMs — co-resident
#define THREADS     256
#define NTHREADS    (GRID_BLOCKS * THREADS)

#define LOG2E 1.4426950408889634f
#define LN2   0.6931471805599453f
#define QSCALE   128.0f             // u16 = -v_log2 * 128, clamp 32767
#define INVQ     (1.0f / 128.0f)
#define MAGIC    8388608.0f         // 2^23
#define MAGIC_HI 0x4B000000u
#define OCLAMPF  (-255.9921875f)    // -32767/128

// Node pool quantized to u16 (71.3 MB — fully L2-resident)
__device__ unsigned short g_node_q[(size_t)TOTAL_NODES * BB];
__device__ float g_partial[NCHUNK * BB];
__device__ uint2 g_pairs[LL * NN * CC];   // row offsets pre-scaled by Q16
__device__ float4 g_wqf[LL * NN];         // pre-scaled weights: w*LOG2E + MAGIC*INVQ

// Grid barrier
__device__ unsigned g_bar_count;
__device__ volatile unsigned g_bar_gen;

__device__ __forceinline__ void grid_sync() {
    __syncthreads();
    if (threadIdx.x == 0) {
        __threadfence();                      // release
        unsigned gen = g_bar_gen;
        if (atomicAdd(&g_bar_count, 1u) == GRID_BLOCKS - 1u) {
            g_bar_count = 0;
            __threadfence();
            g_bar_gen = gen + 1u;
        } else {
            while (g_bar_gen == gen) { }
        }
        __threadfence();                      // acquire: SM-wide L1D invalidate
    }
    __syncthreads();
}

__device__ __forceinline__ float ex2(float x) {
    float r; asm("ex2.approx.ftz.f32 %0, %1;" : "=f"(r) : "f"(x)); return r;
}
__device__ __forceinline__ float lg2(float x) {
    float r; asm("lg2.approx.ftz.f32 %0, %1;" : "=f"(r) : "f"(x)); return r;
}
__device__ __forceinline__ float lse4_2(float a, float b, float c, float d) {
    float m = fmaxf(fmaxf(a, b), fmaxf(c, d));
    float s = ex2(a - m) + ex2(b - m) + ex2(c - m) + ex2(d - m);
    return m + lg2(s);
}
__device__ __forceinline__ float dec_lo(unsigned s, float wq) {
    const float f = __uint_as_float(__byte_perm(s, MAGIC_HI, 0x7610));
    return fmaf(f, -INVQ, wq);
}
__device__ __forceinline__ float dec_hi(unsigned s, float wq) {
    const float f = __uint_as_float(__byte_perm(s, MAGIC_HI, 0x7632));
    return fmaf(f, -INVQ, wq);
}
// encode two outputs -> packed u16x2 via float-magic (FMNMX+FMA each, then PRMT)
__device__ __forceinline__ unsigned enc_pack(float ol, float oh) {
    const unsigned bl = __float_as_uint(fmaf(fmaxf(ol, OCLAMPF), -QSCALE, MAGIC));
    const unsigned bh = __float_as_uint(fmaf(fmaxf(oh, OCLAMPF), -QSCALE, MAGIC));
    return __byte_perm(bl, bh, 0x5410);
}
__device__ __forceinline__ unsigned enc1(float v_log2) {
    unsigned q = __float2uint_rn(-v_log2 * QSCALE);
    return umin(q, 32767u);
}

// LSE over 4 children for one u16x2 word (2 batch columns) -> packed u16x2 out
__device__ __forceinline__ unsigned lse_pack(unsigned s0, unsigned s1,
                                             unsigned s2, unsigned s3,
                                             const float4 wq) {
    const float x0l = dec_lo(s0, wq.x), x0h = dec_hi(s0, wq.x);
    const float x1l = dec_lo(s1, wq.y), x1h = dec_hi(s1, wq.y);
    const float x2l = dec_lo(s2, wq.z), x2h = dec_hi(s2, wq.z);
    const float x3l = dec_lo(s3, wq.w), x3h = dec_hi(s3, wq.w);
    const float ol = lse4_2(x0l, x1l, x2l, x3l);
    const float oh = lse4_2(x0h, x1h, x2h, x3h);
    return enc_pack(ol, oh);
}

// ---- pipeline stages --------------------------------------------------------
struct Data { uint4 a0, q0, a1, q1, a2, q2, a3, q3; };   // 32 regs in flight
struct Sums { uint4 c0, c1, c2, c3; };                   // 16 regs carried

__device__ __forceinline__ void gather(Data& d, const unsigned* s_pairs, int local,
                                       const uint4* __restrict__ nq, unsigned c16) {
    const uint4 pa = *reinterpret_cast<const uint4*>(s_pairs + local * 8);
    const uint4 pb = *reinterpret_cast<const uint4*>(s_pairs + local * 8 + 4);
    d.a0 = __ldg(nq + pa.x + c16);
    d.q0 = __ldg(nq + pa.y + c16);
    d.a1 = __ldg(nq + pa.z + c16);
    d.q1 = __ldg(nq + pa.w + c16);
    d.a2 = __ldg(nq + pb.x + c16);
    d.q2 = __ldg(nq + pb.y + c16);
    d.a3 = __ldg(nq + pb.z + c16);
    d.q3 = __ldg(nq + pb.w + c16);
}

__device__ __forceinline__ void reduce(Sums& s, const Data& d) {
    s.c0.x = __vadd2(d.a0.x, d.q0.x); s.c0.y = __vadd2(d.a0.y, d.q0.y);
    s.c0.z = __vadd2(d.a0.z, d.q0.z); s.c0.w = __vadd2(d.a0.w, d.q0.w);
    s.c1.x = __vadd2(d.a1.x, d.q1.x); s.c1.y = __vadd2(d.a1.y, d.q1.y);
    s.c1.z = __vadd2(d.a1.z, d.q1.z); s.c1.w = __vadd2(d.a1.w, d.q1.w);
    s.c2.x = __vadd2(d.a2.x, d.q2.x); s.c2.y = __vadd2(d.a2.y, d.q2.y);
    s.c2.z = __vadd2(d.a2.z, d.q2.z); s.c2.w = __vadd2(d.a2.w, d.q2.w);
    s.c3.x = __vadd2(d.a3.x, d.q3.x); s.c3.y = __vadd2(d.a3.y, d.q3.y);
    s.c3.z = __vadd2(d.a3.z, d.q3.z); s.c3.w = __vadd2(d.a3.w, d.q3.w);
}

__device__ __forceinline__ void compute_store(const Sums& s, const float4 wq,
                                              uint4* __restrict__ nqo,
                                              unsigned row, unsigned c16) {
    uint4 o;
    o.x = lse_pack(s.c0.x, s.c1.x, s.c2.x, s.c3.x, wq);
    o.y = lse_pack(s.c0.y, s.c1.y, s.c2.y, s.c3.y, wq);
    o.z = lse_pack(s.c0.z, s.c1.z, s.c2.z, s.c3.z, wq);
    o.w = lse_pack(s.c0.w, s.c1.w, s.c2.w, s.c3.w, wq);
    nqo[row * Q16 + c16] = o;
}

__global__ void __launch_bounds__(THREADS, 4)
circuit_kernel(const int* __restrict__ inputs,
               const float* __restrict__ input_logp,
               const int2* __restrict__ prod_ids,     // (L, E)
               const int* __restrict__ sum_ch_ids,    // (L, N, C)
               const float4* __restrict__ sum_logw,   // (L, N) as float4
               const float* __restrict__ root_logw,   // (N,)
               float* __restrict__ out) {
    const int gtid = blockIdx.x * THREADS + threadIdx.x;

    __shared__ unsigned s_pairs[MAX_NPB * 8];
    __shared__ float4   s_w[MAX_NPB];

    // ---------- Phase 0: input quantize + resolve + weight prescale ------------
    for (int idx = gtid; idx < NUM_INPUT * BB; idx += NTHREADS) {
        const int v = idx >> 15;
        const int k = (idx >> 10) & (KK - 1);
        const int b = idx & (BB - 1);
        const int cat = __ldg(inputs + b * NUM_VARS + v);
        const float lp2 = __ldg(input_logp + ((v * KK + k) << 8) + cat) * LOG2E;
        g_node_q[idx] = (unsigned short)enc1(lp2);
    }
    for (int idx = gtid; idx < LL * NN * CC; idx += NTHREADS) {
        const int l = idx / (NN * CC);
        const int e = __ldg(sum_ch_ids + idx);
        const int2 p = __ldg(prod_ids + (size_t)l * EE + e);
        g_pairs[idx] = make_uint2((unsigned)p.x * Q16, (unsigned)p.y * Q16);
    }
    for (int idx = gtid; idx < LL * NN; idx += NTHREADS) {
        const float4 w = __ldg(sum_logw + idx);
        float4 wq;
        wq.x = fmaf(w.x, LOG2E, MAGIC * INVQ);
        wq.y = fmaf(w.y, LOG2E, MAGIC * INVQ);
        wq.z = fmaf(w.z, LOG2E, MAGIC * INVQ);
        wq.w = fmaf(w.w, LOG2E, MAGIC * INVQ);
        g_wqf[idx] = wq;
    }
    grid_sync();

    // ---------- Phases 1..4: sum layers — uint4 + explicit pipeline ------------
    const uint4* nq = reinterpret_cast<const uint4*>(g_node_q);
    uint4* nqo = reinterpret_cast<uint4*>(g_node_q);
    const unsigned c16 = threadIdx.x & 127;   // uint4-column 0..127
    const int half = threadIdx.x >> 7;        // 0 or 1: node parity within block

    const int start = (int)(((long long)blockIdx.x * NN) / GRID_BLOCKS);
    const int end   = (int)(((long long)(blockIdx.x + 1) * NN) / GRID_BLOCKS);
    const int cnt   = end - start;            // 13 or 14
    const int myc   = (cnt - half + 1) >> 1;  // nodes for this half-block (6 or 7)

    for (int l = 0; l < LL; l++) {
        const unsigned out_row0 = (unsigned)(NUM_INPUT + l * NN + start);
        const unsigned* gp = reinterpret_cast<const unsigned*>(g_pairs + (size_t)l * NN * CC);
        const float* gw = reinterpret_cast<const float*>(g_wqf + (size_t)l * NN);

        for (int t = threadIdx.x; t < cnt * 8; t += THREADS)
            s_pairs[t] = gp[start * 8 + t];
        for (int t = threadIdx.x; t < cnt * 4; t += THREADS)
            reinterpret_cast<float*>(s_w)[t] = gw[start * 4 + t];
        __syncthreads();

        // pipeline: reduce(A); gather(B); compute(A) — one 32-reg load set in flight
        Data d;
        Sums s;
        gather(d, s_pairs, half, nq, c16);         // node j=0 (local = half)
        reduce(s, d);
        for (int j = 0; j < myc; j++) {
            const int nxt = 2 * (j + 1) + half;
            const bool more = (j + 1) < myc;
            if (more) gather(d, s_pairs, nxt, nq, c16);
            compute_store(s, s_w[2 * j + half], nqo,
                          out_row0 + 2 * j + half, c16);
            if (more) reduce(s, d);
        }
        grid_sync();
    }

    // ---------- Phase 5: root partial logsumexp (decode u16, float) -----------
    {
        const unsigned short* last = g_node_q + (size_t)(NUM_INPUT + (LL - 1) * NN) * BB;
        const int idx = gtid;
        if (idx < NCHUNK * BB) {
            const int chunk = idx >> 10;
            const int b = idx & (BB - 1);
            const int n0 = chunk * (NN / NCHUNK);
            float m = -CUDART_INF_F, s = 0.f;
#pragma unroll 4
            for (int i2 = 0; i2 < NN / NCHUNK; i2++) {
                const int n = n0 + i2;
                const float nv = -(float)last[(unsigned)n * BB + b] * INVQ;
                const float x = fmaf(__ldg(root_logw + n), LOG2E, nv);
                const float mn = fmaxf(m, x);
                s = s * ex2(m - mn) + ex2(x - mn);
                m = mn;
            }
            g_partial[chunk * BB + b] = m + lg2(s);
        }
    }
    grid_sync();

    // ---------- Phase 6: final combine (-> natural log) -----------------------
    {
        const int wgid = gtid >> 5;
        const int lane = gtid & 31;
        if (wgid < BB) {
            const int b = wgid;
            const float x0 = g_partial[lane * BB + b];
            const float x1 = g_partial[(lane + 32) * BB + b];
            float m = fmaxf(x0, x1);
#pragma unroll
            for (int o = 16; o > 0; o >>= 1)
                m = fmaxf(m, __shfl_xor_sync(0xFFFFFFFF, m, o));
            float s = ex2(x0 - m) + ex2(x1 - m);
#pragma unroll
            for (int o = 16; o > 0; o >>= 1)
                s += __shfl_xor_sync(0xFFFFFFFF, s, o);
            if (lane == 0) out[b] = (m + lg2(s)) * LN2;
        }
    }
}

// ---------------------------------------------------------------------------
extern "C" void kernel_launch(void* const* d_in, const int* in_sizes, int n_in,
                              void* d_out, int out_size) {
    const int*   inputs     = (const int*)  d_in[0];
    const float* input_logp = (const float*)d_in[1];
    const int*   prod_ids   = (const int*)  d_in[2];  // (L, E, 2)
    const int*   sum_ch_ids = (const int*)  d_in[3];  // (L, N, C)
    const float* sum_logw   = (const float*)d_in[4];  // (L, N, C)
    const float* root_logw  = (const float*)d_in[5];  // (N,)
    float* out = (float*)d_out;

    circuit_kernel<<<GRID_BLOCKS, THREADS>>>(
        inputs, input_logp,
        reinterpret_cast<const int2*>(prod_ids),
        sum_ch_ids,
        reinterpret_cast<const float4*>(sum_logw),
        root_logw, out);
}

// round 16
// speedup vs baseline: 1.1495x; 1.1495x over previous
#include <cuda_runtime.h>
#include <math_constants.h>

// Problem constants
#define NUM_VARS 64
#define KK       32
#define NUM_CATS 256
#define NUM_INPUT (NUM_VARS * KK)   // 2048
#define LL       4
#define EE       16384
#define NN       8192
#define CC       4
#define BB       1024
#define Q16      128                // uint4-groups per row (1024 u16 = 128 x 16B)
#define TOTAL_NODES (NUM_INPUT + LL * NN)  // 34816
#define NCHUNK   128                // root reduction chunks (chain length 64)
#define MAX_NPB  14                 // max nodes per block per layer

#define GRID_BLOCKS 592             // 4 blocks/SM on 148 SMs — co-resident
#define THREADS     256
#define NTHREADS    (GRID_BLOCKS * THREADS)

#define LOG2E 1.4426950408889634f
#define LN2   0.6931471805599453f
#define QSCALE   128.0f             // u16 = -v_log2 * 128, clamp 32767
#define INVQ     (1.0f / 128.0f)
#define MAGIC    8388608.0f         // 2^23
#define MAGIC_HI 0x4B000000u
#define OCLAMPF  (-255.9921875f)    // -32767/128

// Node pool quantized to u16 (71.3 MB — fully L2-resident)
__device__ unsigned short g_node_q[(size_t)TOTAL_NODES * BB];
__device__ float g_partial[NCHUNK * BB];
__device__ uint2 g_pairs[LL * NN * CC];   // row offsets pre-scaled by Q16
__device__ float4 g_wqf[LL * NN];         // pre-scaled weights: w*LOG2E + MAGIC*INVQ

// Grid barrier
__device__ unsigned g_bar_count;
__device__ volatile unsigned g_bar_gen;

__device__ __forceinline__ void grid_sync() {
    __syncthreads();
    if (threadIdx.x == 0) {
        __threadfence();                      // release
        unsigned gen = g_bar_gen;
        if (atomicAdd(&g_bar_count, 1u) == GRID_BLOCKS - 1u) {
            g_bar_count = 0;
            __threadfence();
            g_bar_gen = gen + 1u;
        } else {
            while (g_bar_gen == gen) { }
        }
        __threadfence();                      // acquire: SM-wide L1D invalidate
    }
    __syncthreads();
}

__device__ __forceinline__ float ex2(float x) {
    float r; asm("ex2.approx.ftz.f32 %0, %1;" : "=f"(r) : "f"(x)); return r;
}
__device__ __forceinline__ float lg2(float x) {
    float r; asm("lg2.approx.ftz.f32 %0, %1;" : "=f"(r) : "f"(x)); return r;
}
__device__ __forceinline__ float lse4_2(float a, float b, float c, float d) {
    float m = fmaxf(fmaxf(a, b), fmaxf(c, d));
    float s = ex2(a - m) + ex2(b - m) + ex2(c - m) + ex2(d - m);
    return m + lg2(s);
}
__device__ __forceinline__ float dec_lo(unsigned s, float wq) {
    const float f = __uint_as_float(__byte_perm(s, MAGIC_HI, 0x7610));
    return fmaf(f, -INVQ, wq);
}
__device__ __forceinline__ float dec_hi(unsigned s, float wq) {
    const float f = __uint_as_float(__byte_perm(s, MAGIC_HI, 0x7632));
    return fmaf(f, -INVQ, wq);
}
// encode two outputs -> packed u16x2 via float-magic (FMNMX+FMA each, then PRMT)
__device__ __forceinline__ unsigned enc_pack(float ol, float oh) {
    const unsigned bl = __float_as_uint(fmaf(fmaxf(ol, OCLAMPF), -QSCALE, MAGIC));
    const unsigned bh = __float_as_uint(fmaf(fmaxf(oh, OCLAMPF), -QSCALE, MAGIC));
    return __byte_perm(bl, bh, 0x5410);
}
__device__ __forceinline__ unsigned enc1(float v_log2) {
    unsigned q = __float2uint_rn(-v_log2 * QSCALE);
    return umin(q, 32767u);
}

// LSE over 4 children for one u16x2 word (2 batch columns) -> packed u16x2 out
__device__ __forceinline__ unsigned lse_pack(unsigned s0, unsigned s1,
                                             unsigned s2, unsigned s3,
                                             float wq0, float wq1,
                                             float wq2, float wq3) {
    const float x0l = dec_lo(s0, wq0), x0h = dec_hi(s0, wq0);
    const float x1l = dec_lo(s1, wq1), x1h = dec_hi(s1, wq1);
    const float x2l = dec_lo(s2, wq2), x2h = dec_hi(s2, wq2);
    const float x3l = dec_lo(s3, wq3), x3h = dec_hi(s3, wq3);
    const float ol = lse4_2(x0l, x1l, x2l, x3l);
    const float oh = lse4_2(x0h, x1h, x2h, x3h);
    return enc_pack(ol, oh);
}

__global__ void __launch_bounds__(THREADS, 4)
circuit_kernel(const int* __restrict__ inputs,
               const float* __restrict__ input_logp,
               const int2* __restrict__ prod_ids,     // (L, E)
               const int* __restrict__ sum_ch_ids,    // (L, N, C)
               const float4* __restrict__ sum_logw,   // (L, N) as float4
               const float* __restrict__ root_logw,   // (N,)
               float* __restrict__ out) {
    const int gtid = blockIdx.x * THREADS + threadIdx.x;

    __shared__ unsigned s_pairs[MAX_NPB * 8];
    __shared__ float4   s_w[MAX_NPB];

    // ---------- Phase 0: input quantize + resolve + weight prescale ------------
    for (int idx = gtid; idx < NUM_INPUT * BB; idx += NTHREADS) {
        const int v = idx >> 15;
        const int k = (idx >> 10) & (KK - 1);
        const int b = idx & (BB - 1);
        const int cat = __ldg(inputs + b * NUM_VARS + v);
        const float lp2 = __ldg(input_logp + ((v * KK + k) << 8) + cat) * LOG2E;
        g_node_q[idx] = (unsigned short)enc1(lp2);
    }
    for (int idx = gtid; idx < LL * NN * CC; idx += NTHREADS) {
        const int l = idx / (NN * CC);
        const int e = __ldg(sum_ch_ids + idx);
        const int2 p = __ldg(prod_ids + (size_t)l * EE + e);
        g_pairs[idx] = make_uint2((unsigned)p.x * Q16, (unsigned)p.y * Q16);
    }
    for (int idx = gtid; idx < LL * NN; idx += NTHREADS) {
        const float4 w = __ldg(sum_logw + idx);
        float4 wq;
        wq.x = fmaf(w.x, LOG2E, MAGIC * INVQ);
        wq.y = fmaf(w.y, LOG2E, MAGIC * INVQ);
        wq.z = fmaf(w.z, LOG2E, MAGIC * INVQ);
        wq.w = fmaf(w.w, LOG2E, MAGIC * INVQ);
        g_wqf[idx] = wq;
    }
    grid_sync();

    // ---------- Phases 1..4: sum layers — uint4 gathers, half-block per node ---
    const uint4* nq = reinterpret_cast<const uint4*>(g_node_q);
    uint4* nqo = reinterpret_cast<uint4*>(g_node_q);
    const unsigned c16 = threadIdx.x & 127;   // uint4-column 0..127
    const int half = threadIdx.x >> 7;        // 0 or 1: which node of the pair

    const int start = (int)(((long long)blockIdx.x * NN) / GRID_BLOCKS);
    const int end   = (int)(((long long)(blockIdx.x + 1) * NN) / GRID_BLOCKS);
    const int cnt   = end - start;            // 13 or 14
    const int iters = (cnt + 1) >> 1;

    for (int l = 0; l < LL; l++) {
        const int out_base = NUM_INPUT + l * NN;
        const unsigned* gp = reinterpret_cast<const unsigned*>(g_pairs + (size_t)l * NN * CC);
        const float* gw = reinterpret_cast<const float*>(g_wqf + (size_t)l * NN);

        for (int t = threadIdx.x; t < cnt * 8; t += THREADS)
            s_pairs[t] = gp[start * 8 + t];
        for (int t = threadIdx.x; t < cnt * 4; t += THREADS)
            reinterpret_cast<float*>(s_w)[t] = gw[start * 4 + t];
        __syncthreads();

#pragma unroll 2
        for (int i = 0; i < iters; i++) {
            const int local = i * 2 + half;
            const int n = start + local;
            if (n < end) {
                const uint4 pa = *reinterpret_cast<const uint4*>(s_pairs + local * 8);
                const uint4 pb = *reinterpret_cast<const uint4*>(s_pairs + local * 8 + 4);
                const float4 wq = s_w[local];

                const uint4 a0 = __ldg(nq + pa.x + c16);
                const uint4 q0 = __ldg(nq + pa.y + c16);
                const uint4 a1 = __ldg(nq + pa.z + c16);
                const uint4 q1 = __ldg(nq + pa.w + c16);
                const uint4 a2 = __ldg(nq + pb.x + c16);
                const uint4 q2 = __ldg(nq + pb.y + c16);
                const uint4 a3 = __ldg(nq + pb.z + c16);
                const uint4 q3 = __ldg(nq + pb.w + c16);

                uint4 o;
                o.x = lse_pack(__vadd2(a0.x, q0.x), __vadd2(a1.x, q1.x),
                               __vadd2(a2.x, q2.x), __vadd2(a3.x, q3.x),
                               wq.x, wq.y, wq.z, wq.w);
                o.y = lse_pack(__vadd2(a0.y, q0.y), __vadd2(a1.y, q1.y),
                               __vadd2(a2.y, q2.y), __vadd2(a3.y, q3.y),
                               wq.x, wq.y, wq.z, wq.w);
                o.z = lse_pack(__vadd2(a0.z, q0.z), __vadd2(a1.z, q1.z),
                               __vadd2(a2.z, q2.z), __vadd2(a3.z, q3.z),
                               wq.x, wq.y, wq.z, wq.w);
                o.w = lse_pack(__vadd2(a0.w, q0.w), __vadd2(a1.w, q1.w),
                               __vadd2(a2.w, q2.w), __vadd2(a3.w, q3.w),
                               wq.x, wq.y, wq.z, wq.w);

                nqo[(unsigned)(out_base + n) * Q16 + c16] = o;
            }
        }
        grid_sync();
    }

    // ---------- Phase 5: root partial logsumexp (decode u16, float) -----------
    {
        const unsigned short* last = g_node_q + (size_t)(NUM_INPUT + (LL - 1) * NN) * BB;
        const int idx = gtid;
        if (idx < NCHUNK * BB) {
            const int chunk = idx >> 10;
            const int b = idx & (BB - 1);
            const int n0 = chunk * (NN / NCHUNK);
            float m = -CUDART_INF_F, s = 0.f;
#pragma unroll 4
            for (int i2 = 0; i2 < NN / NCHUNK; i2++) {
                const int n = n0 + i2;
                const float nv = -(float)last[(unsigned)n * BB + b] * INVQ;
                const float x = fmaf(__ldg(root_logw + n), LOG2E, nv);
                const float mn = fmaxf(m, x);
                s = s * ex2(m - mn) + ex2(x - mn);
                m = mn;
            }
            g_partial[chunk * BB + b] = m + lg2(s);
        }
    }
    grid_sync();

    // ---------- Phase 6: final combine (warp per column, 128 partials) --------
    {
        const int wgid = gtid >> 5;
        const int lane = gtid & 31;
        if (wgid < BB) {
            const int b = wgid;
            const float x0 = g_partial[lane * BB + b];
            const float x1 = g_partial[(lane + 32) * BB + b];
            const float x2 = g_partial[(lane + 64) * BB + b];
            const float x3 = g_partial[(lane + 96) * BB + b];
            float m = fmaxf(fmaxf(x0, x1), fmaxf(x2, x3));
#pragma unroll
            for (int o = 16; o > 0; o >>= 1)
                m = fmaxf(m, __shfl_xor_sync(0xFFFFFFFF, m, o));
            float s = ex2(x0 - m) + ex2(x1 - m) + ex2(x2 - m) + ex2(x3 - m);
#pragma unroll
            for (int o = 16; o > 0; o >>= 1)
                s += __shfl_xor_sync(0xFFFFFFFF, s, o);
            if (lane == 0) out[b] = (m + lg2(s)) * LN2;
        }
    }
}

// ---------------------------------------------------------------------------
extern "C" void kernel_launch(void* const* d_in, const int* in_sizes, int n_in,
                              void* d_out, int out_size) {
    const int*   inputs     = (const int*)  d_in[0];
    const float* input_logp = (const float*)d_in[1];
    const int*   prod_ids   = (const int*)  d_in[2];  // (L, E, 2)
    const int*   sum_ch_ids = (const int*)  d_in[3];  // (L, N, C)
    const float* sum_logw   = (const float*)d_in[4];  // (L, N, C)
    const float* root_logw  = (const float*)d_in[5];  // (N,)
    float* out = (float*)d_out;

    circuit_kernel<<<GRID_BLOCKS, THREADS>>>(
        inputs, input_logp,
        reinterpret_cast<const int2*>(prod_ids),
        sum_ch_ids,
        reinterpret_cast<const float4*>(sum_logw),
        root_logw, out);
}